// round 3
// baseline (speedup 1.0000x reference)
#include <cuda_runtime.h>

// LSTMAutoencoder: B=4096, T=512, F=8, H=16
// enc LSTM -> hT -> repeat -> dec LSTM -> linear
//
// Layout: 16 lanes per batch element (lane j owns hidden unit j and gate rows
// j, 16+j, 32+j, 48+j). 2 batch elements per warp, 8 per 128-thread block.
// h state broadcast via double-buffered smem row + one __syncwarp per step.
// All matvec FMAs are packed fp32x2 (Blackwell FFMA2).

using ull = unsigned long long;

#define Bsz 4096
#define Tsz 512
#define Fsz 8
#define Hsz 16
#define GROUPS_PER_BLOCK 8
#define THREADS (GROUPS_PER_BLOCK * 16)

__device__ __forceinline__ void fma2(ull& d, ull a, ull b) {
    asm("fma.rn.f32x2 %0, %1, %2, %0;" : "+l"(d) : "l"(a), "l"(b));
}
__device__ __forceinline__ ull pk(float lo, float hi) {
    ull r; asm("mov.b64 %0, {%1, %2};" : "=l"(r) : "f"(lo), "f"(hi)); return r;
}
__device__ __forceinline__ float redu(ull a) {   // lo + hi
    float lo, hi; asm("mov.b64 {%0, %1}, %2;" : "=f"(lo), "=f"(hi) : "l"(a));
    return lo + hi;
}
__device__ __forceinline__ float ex2f_(float x){ float y; asm("ex2.approx.f32 %0, %1;" : "=f"(y) : "f"(x)); return y; }
__device__ __forceinline__ float rcpf_(float x){ float y; asm("rcp.approx.f32 %0, %1;" : "=f"(y) : "f"(x)); return y; }
// sigmoid(x) = 1/(1+e^-x);  e^-x = 2^(-x*log2e)
__device__ __forceinline__ float sigm(float x){ return rcpf_(1.0f + ex2f_(-1.4426950408889634f * x)); }
// tanh(x) = 1 - 2/(e^(2x)+1)
__device__ __forceinline__ float tanhf_(float x){ return 1.0f - 2.0f * rcpf_(1.0f + ex2f_(2.8853900817779268f * x)); }

__global__ void __launch_bounds__(THREADS, 4)
lstm_ae(const float* __restrict__ x,
        const float* __restrict__ eWih, const float* __restrict__ eWhh,
        const float* __restrict__ eBih, const float* __restrict__ eBhh,
        const float* __restrict__ dWih, const float* __restrict__ dWhh,
        const float* __restrict__ dBih, const float* __restrict__ dBhh,
        const float* __restrict__ oW,  const float* __restrict__ oB,
        float* __restrict__ out)
{
    __shared__ __align__(16) float hbuf[2][GROUPS_PER_BLOCK][Hsz];
    const int j   = threadIdx.x & 15;          // hidden unit owned by this lane
    const int grp = threadIdx.x >> 4;          // batch group within block
    const long b  = (long)blockIdx.x * GROUPS_PER_BLOCK + grp;

    // ---------------- encoder weights into registers (packed pairs) --------
    ull whh[4][8];      // 4 gate rows x 16 (8 f32x2 pairs)
    ull wih[4][4];      // 4 gate rows x 8
    float bias[4];
    #pragma unroll
    for (int g = 0; g < 4; ++g) {
        const int row = g * Hsz + j;
        const ull* wr = reinterpret_cast<const ull*>(eWhh + row * Hsz);
        #pragma unroll
        for (int p = 0; p < 8; ++p) whh[g][p] = wr[p];
        const ull* wi = reinterpret_cast<const ull*>(eWih + row * Fsz);
        #pragma unroll
        for (int p = 0; p < 4; ++p) wih[g][p] = wi[p];
        bias[g] = eBih[row] + eBhh[row];
    }

    // zero initial state buffer (step 0 reads hbuf[0])
    hbuf[0][grp][j] = 0.0f;
    __syncwarp();

    const float* xptr = x + ((long)b * Tsz) * Fsz;
    float c = 0.0f;

    // ---------------- encoder recurrence ----------------
    #pragma unroll 1
    for (int t = 0; t < Tsz; ++t) {
        const int rb = t & 1;
        ull xv[4];
        const ull* px = reinterpret_cast<const ull*>(xptr);
        #pragma unroll
        for (int p = 0; p < 4; ++p) xv[p] = px[p];
        xptr += Fsz;

        ull a0 = pk(bias[0], 0.0f), a1 = pk(bias[1], 0.0f),
            a2 = pk(bias[2], 0.0f), a3 = pk(bias[3], 0.0f);
        #pragma unroll
        for (int p = 0; p < 4; ++p) {          // input projection
            fma2(a0, wih[0][p], xv[p]);
            fma2(a1, wih[1][p], xv[p]);
            fma2(a2, wih[2][p], xv[p]);
            fma2(a3, wih[3][p], xv[p]);
        }
        const ull* hr = reinterpret_cast<const ull*>(&hbuf[rb][grp][0]);
        #pragma unroll
        for (int p = 0; p < 8; ++p) {          // recurrence h @ Whh^T
            ull hp = hr[p];
            fma2(a0, whh[0][p], hp);
            fma2(a1, whh[1][p], hp);
            fma2(a2, whh[2][p], hp);
            fma2(a3, whh[3][p], hp);
        }
        const float gi = sigm(redu(a0));
        const float gf = sigm(redu(a1));
        const float gg = tanhf_(redu(a2));
        const float go = sigm(redu(a3));
        c = gf * c + gi * gg;
        const float h = go * tanhf_(c);
        hbuf[rb ^ 1][grp][j] = h;
        __syncwarp();
    }
    // final encoder state hT sits in hbuf[0] (512 is even)

    // ---------------- decoder prep ----------------
    ull hp8[8];
    {
        const ull* hr0 = reinterpret_cast<const ull*>(&hbuf[0][grp][0]);
        #pragma unroll
        for (int p = 0; p < 8; ++p) hp8[p] = hr0[p];
    }
    // decoder input is constant over t: xpd = dWih @ hT + (dBih + dBhh)
    float xpd[4];
    #pragma unroll
    for (int g = 0; g < 4; ++g) {
        const int row = g * Hsz + j;
        ull acc = pk(dBih[row] + dBhh[row], 0.0f);
        const ull* wr = reinterpret_cast<const ull*>(dWih + row * Hsz);
        #pragma unroll
        for (int p = 0; p < 8; ++p) fma2(acc, wr[p], hp8[p]);
        xpd[g] = redu(acc);
        const ull* wh = reinterpret_cast<const ull*>(dWhh + row * Hsz);
        #pragma unroll
        for (int p = 0; p < 8; ++p) whh[g][p] = wh[p];   // reload recurrence wts
    }
    // output-linear row for this lane (lanes 8..15 compute-but-don't-store)
    ull owp[8];
    {
        const int f = j & 7;
        const ull* wr = reinterpret_cast<const ull*>(oW + f * Hsz);
        #pragma unroll
        for (int p = 0; p < 8; ++p) owp[p] = wr[p];
    }
    const float outb = oB[j & 7];

    c = 0.0f;
    __syncwarp();                 // everyone done reading hT
    hbuf[0][grp][j] = 0.0f;       // decoder h0 = 0
    __syncwarp();

    float* po = out + ((long)b * Tsz) * Fsz + j;

    // ---------------- decoder recurrence + fused output linear -------------
    #pragma unroll 1
    for (int t = 0; t < Tsz; ++t) {
        const int rb = t & 1;
        ull a0 = pk(xpd[0], 0.0f), a1 = pk(xpd[1], 0.0f),
            a2 = pk(xpd[2], 0.0f), a3 = pk(xpd[3], 0.0f);
        const ull* hr = reinterpret_cast<const ull*>(&hbuf[rb][grp][0]);
        #pragma unroll
        for (int p = 0; p < 8; ++p) {
            ull hp = hr[p];
            fma2(a0, whh[0][p], hp);
            fma2(a1, whh[1][p], hp);
            fma2(a2, whh[2][p], hp);
            fma2(a3, whh[3][p], hp);
        }
        const float gi = sigm(redu(a0));
        const float gf = sigm(redu(a1));
        const float gg = tanhf_(redu(a2));
        const float go = sigm(redu(a3));
        c = gf * c + gi * gg;
        const float h = go * tanhf_(c);
        hbuf[rb ^ 1][grp][j] = h;
        __syncwarp();

        // out[b,t,:] = oW @ h_new + oB  (read the just-published state)
        ull oacc = pk(outb, 0.0f);
        const ull* hn = reinterpret_cast<const ull*>(&hbuf[rb ^ 1][grp][0]);
        #pragma unroll
        for (int p = 0; p < 8; ++p) fma2(oacc, owp[p], hn[p]);
        if (j < 8) po[(long)t * Fsz] = redu(oacc);
    }
}

extern "C" void kernel_launch(void* const* d_in, const int* in_sizes, int n_in,
                              void* d_out, int out_size) {
    (void)in_sizes; (void)n_in; (void)out_size;
    lstm_ae<<<Bsz / GROUPS_PER_BLOCK, THREADS>>>(
        (const float*)d_in[0],                       // x
        (const float*)d_in[1], (const float*)d_in[2],// enc_Wih, enc_Whh
        (const float*)d_in[3], (const float*)d_in[4],// enc_bih, enc_bhh
        (const float*)d_in[5], (const float*)d_in[6],// dec_Wih, dec_Whh
        (const float*)d_in[7], (const float*)d_in[8],// dec_bih, dec_bhh
        (const float*)d_in[9], (const float*)d_in[10],// out_W, out_b
        (float*)d_out);
}

// round 4
// speedup vs baseline: 1.1421x; 1.1421x over previous
#include <cuda_runtime.h>

// LSTMAutoencoder: B=4096, T=512, F=8, H=16
// enc LSTM -> hT -> repeat -> dec LSTM -> fused linear
//
// 16 lanes per batch element (lane j owns hidden unit j / gate rows j,16+j,
// 32+j,48+j). 4 batch elements per 64-thread block -> 1024 blocks (balanced
// 7-vs-6 across 148 SMs). h broadcast via double-buffered smem row + one
// __syncwarp per step. All matvecs are packed fp32x2 (FFMA2).
// Activation-arg scales (-log2e for sigmoids, 2*log2e for tanh) are folded
// into the weights/biases at load time; c is kept in the 2*log2e domain.

using ull = unsigned long long;

#define Bsz 4096
#define Tsz 512
#define Fsz 8
#define Hsz 16
#define GPB 4
#define THREADS (GPB * 16)

#define L2E 1.4426950408889634f

__device__ __forceinline__ void fma2(ull& d, ull a, ull b) {
    asm("fma.rn.f32x2 %0, %1, %2, %0;" : "+l"(d) : "l"(a), "l"(b));
}
__device__ __forceinline__ ull fma2a(ull a, ull b, ull c) {
    ull r; asm("fma.rn.f32x2 %0, %1, %2, %3;" : "=l"(r) : "l"(a), "l"(b), "l"(c)); return r;
}
__device__ __forceinline__ ull mul2(ull a, ull b) {
    ull r; asm("mul.rn.f32x2 %0, %1, %2;" : "=l"(r) : "l"(a), "l"(b)); return r;
}
__device__ __forceinline__ ull pk(float lo, float hi) {
    ull r; asm("mov.b64 %0, {%1, %2};" : "=l"(r) : "f"(lo), "f"(hi)); return r;
}
__device__ __forceinline__ float redu(ull a) {   // lo + hi
    float lo, hi; asm("mov.b64 {%0, %1}, %2;" : "=f"(lo), "=f"(hi) : "l"(a));
    return lo + hi;
}
__device__ __forceinline__ float ex2f_(float x){ float y; asm("ex2.approx.f32 %0, %1;" : "=f"(y) : "f"(x)); return y; }
__device__ __forceinline__ float rcpf_(float x){ float y; asm("rcp.approx.f32 %0, %1;" : "=f"(y) : "f"(x)); return y; }

__global__ void __launch_bounds__(THREADS, 7)
lstm_ae(const float* __restrict__ x,
        const float* __restrict__ eWih, const float* __restrict__ eWhh,
        const float* __restrict__ eBih, const float* __restrict__ eBhh,
        const float* __restrict__ dWih, const float* __restrict__ dWhh,
        const float* __restrict__ dBih, const float* __restrict__ dBhh,
        const float* __restrict__ oW,  const float* __restrict__ oB,
        float* __restrict__ out)
{
    __shared__ __align__(16) float hbuf[2][GPB][Hsz];
    const int j   = threadIdx.x & 15;
    const int grp = threadIdx.x >> 4;
    const long b  = (long)blockIdx.x * GPB + grp;

    const ull sgS = pk(-L2E, -L2E);          // sigmoid gates
    const ull sgG = pk(2.0f*L2E, 2.0f*L2E);  // tanh gate

    // ---------------- encoder weights (pre-scaled, packed) ----------------
    ull whh[4][8];
    ull wih[4][4];
    ull biaspk[4];
    #pragma unroll
    for (int g = 0; g < 4; ++g) {
        const ull  sc  = (g == 2) ? sgG : sgS;
        const float scf = (g == 2) ? 2.0f*L2E : -L2E;
        const int row = g * Hsz + j;
        const ull* wr = reinterpret_cast<const ull*>(eWhh + row * Hsz);
        #pragma unroll
        for (int p = 0; p < 8; ++p) whh[g][p] = mul2(wr[p], sc);
        const ull* wi = reinterpret_cast<const ull*>(eWih + row * Fsz);
        #pragma unroll
        for (int p = 0; p < 4; ++p) wih[g][p] = mul2(wi[p], sc);
        biaspk[g] = pk(scf * (eBih[row] + eBhh[row]), 0.0f);
    }

    hbuf[0][grp][j] = 0.0f;
    __syncwarp();

    const longlong2* px = reinterpret_cast<const longlong2*>(x + (long)b * Tsz * Fsz);
    float cs = 0.0f;   // c in 2*log2e-scaled domain

    // one encoder step: read hin, write hout
    auto estep = [&](const float* hin, float* hout) {
        longlong2 xa = px[0], xb = px[1];
        px += 2;
        ull xv0 = (ull)xa.x, xv1 = (ull)xa.y, xv2 = (ull)xb.x, xv3 = (ull)xb.y;
        ull a0 = fma2a(wih[0][0], xv0, biaspk[0]);
        ull a1 = fma2a(wih[1][0], xv0, biaspk[1]);
        ull a2 = fma2a(wih[2][0], xv0, biaspk[2]);
        ull a3 = fma2a(wih[3][0], xv0, biaspk[3]);
        fma2(a0, wih[0][1], xv1); fma2(a1, wih[1][1], xv1);
        fma2(a2, wih[2][1], xv1); fma2(a3, wih[3][1], xv1);
        fma2(a0, wih[0][2], xv2); fma2(a1, wih[1][2], xv2);
        fma2(a2, wih[2][2], xv2); fma2(a3, wih[3][2], xv2);
        fma2(a0, wih[0][3], xv3); fma2(a1, wih[1][3], xv3);
        fma2(a2, wih[2][3], xv3); fma2(a3, wih[3][3], xv3);
        const ull* hr = reinterpret_cast<const ull*>(hin);
        #pragma unroll
        for (int p = 0; p < 8; ++p) {
            ull hp = hr[p];
            fma2(a0, whh[0][p], hp); fma2(a1, whh[1][p], hp);
            fma2(a2, whh[2][p], hp); fma2(a3, whh[3][p], hp);
        }
        const float r0 = rcpf_(1.0f + ex2f_(redu(a0)));   // i
        const float r1 = rcpf_(1.0f + ex2f_(redu(a1)));   // f
        const float r2 = rcpf_(1.0f + ex2f_(redu(a2)));   // for g
        const float r3 = rcpf_(1.0f + ex2f_(redu(a3)));   // o
        const float gs = fmaf(r2, -4.0f*L2E, 2.0f*L2E);   // 2*log2e * tanh(g)
        cs = fmaf(r1, cs, r0 * gs);
        const float rc = rcpf_(1.0f + ex2f_(cs));
        const float h  = fmaf(r3 * rc, -2.0f, r3);        // o * tanh(c)
        hout[j] = h;
        __syncwarp();
    };

    #pragma unroll 1
    for (int t = 0; t < Tsz; t += 2) {
        estep(&hbuf[0][grp][0], &hbuf[1][grp][0]);
        estep(&hbuf[1][grp][0], &hbuf[0][grp][0]);
    }
    // hT in hbuf[0]

    // ---------------- decoder prep ----------------
    ull hp8[8];
    {
        const ull* hr0 = reinterpret_cast<const ull*>(&hbuf[0][grp][0]);
        #pragma unroll
        for (int p = 0; p < 8; ++p) hp8[p] = hr0[p];
    }
    ull xpdpk[4];
    #pragma unroll
    for (int g = 0; g < 4; ++g) {
        const ull  sc  = (g == 2) ? sgG : sgS;
        const float scf = (g == 2) ? 2.0f*L2E : -L2E;
        const int row = g * Hsz + j;
        ull acc = pk(scf * (dBih[row] + dBhh[row]), 0.0f);
        const ull* wr = reinterpret_cast<const ull*>(dWih + row * Hsz);
        #pragma unroll
        for (int p = 0; p < 8; ++p) fma2(acc, mul2(wr[p], sc), hp8[p]);
        xpdpk[g] = pk(redu(acc), 0.0f);
        const ull* wh = reinterpret_cast<const ull*>(dWhh + row * Hsz);
        #pragma unroll
        for (int p = 0; p < 8; ++p) whh[g][p] = mul2(wh[p], sc);
    }
    ull owp[8];
    const int f = j & 7;
    {
        const ull* orow = reinterpret_cast<const ull*>(oW + f * Hsz);
        #pragma unroll
        for (int p = 0; p < 8; ++p) owp[p] = orow[p];
    }
    const ull outbpk = pk(oB[f], 0.0f);

    cs = 0.0f;
    __syncwarp();                 // all lanes done reading hT
    hbuf[0][grp][j] = 0.0f;       // decoder h0
    __syncwarp();

    float* po = out + (long)b * Tsz * Fsz + f;

    // decoder step: reads hin (= h_{t-1}); when doOut, also emits the output
    // row for step t-1 reusing the same h loads, then computes h_t -> hout.
    auto dstep = [&](const float* hin, float* hout, bool doOut) {
        const ull* hr = reinterpret_cast<const ull*>(hin);
        ull hp[8];
        #pragma unroll
        for (int p = 0; p < 8; ++p) hp[p] = hr[p];
        if (doOut) {
            ull oacc = fma2a(owp[0], hp[0], outbpk);
            #pragma unroll
            for (int p = 1; p < 8; ++p) fma2(oacc, owp[p], hp[p]);
            if (j < 8) { *po = redu(oacc); }
            po += Fsz;
        }
        ull a0 = fma2a(whh[0][0], hp[0], xpdpk[0]);
        ull a1 = fma2a(whh[1][0], hp[0], xpdpk[1]);
        ull a2 = fma2a(whh[2][0], hp[0], xpdpk[2]);
        ull a3 = fma2a(whh[3][0], hp[0], xpdpk[3]);
        #pragma unroll
        for (int p = 1; p < 8; ++p) {
            fma2(a0, whh[0][p], hp[p]); fma2(a1, whh[1][p], hp[p]);
            fma2(a2, whh[2][p], hp[p]); fma2(a3, whh[3][p], hp[p]);
        }
        const float r0 = rcpf_(1.0f + ex2f_(redu(a0)));
        const float r1 = rcpf_(1.0f + ex2f_(redu(a1)));
        const float r2 = rcpf_(1.0f + ex2f_(redu(a2)));
        const float r3 = rcpf_(1.0f + ex2f_(redu(a3)));
        const float gs = fmaf(r2, -4.0f*L2E, 2.0f*L2E);
        cs = fmaf(r1, cs, r0 * gs);
        const float rc = rcpf_(1.0f + ex2f_(cs));
        const float h  = fmaf(r3 * rc, -2.0f, r3);
        hout[j] = h;
        __syncwarp();
    };

    // peel t=0 (no previous h to emit), t=1; then steady unroll-2
    dstep(&hbuf[0][grp][0], &hbuf[1][grp][0], false);   // t=0
    dstep(&hbuf[1][grp][0], &hbuf[0][grp][0], true);    // t=1 emits row 0
    #pragma unroll 1
    for (int t = 2; t < Tsz; t += 2) {
        dstep(&hbuf[0][grp][0], &hbuf[1][grp][0], true);
        dstep(&hbuf[1][grp][0], &hbuf[0][grp][0], true);
    }
    // emit final row (h_{511} sits in hbuf[0])
    {
        const ull* hr = reinterpret_cast<const ull*>(&hbuf[0][grp][0]);
        ull oacc = fma2a(owp[0], hr[0], outbpk);
        #pragma unroll
        for (int p = 1; p < 8; ++p) fma2(oacc, owp[p], hr[p]);
        if (j < 8) { *po = redu(oacc); }
    }
}

extern "C" void kernel_launch(void* const* d_in, const int* in_sizes, int n_in,
                              void* d_out, int out_size) {
    (void)in_sizes; (void)n_in; (void)out_size;
    lstm_ae<<<Bsz / GPB, THREADS>>>(
        (const float*)d_in[0],
        (const float*)d_in[1], (const float*)d_in[2],
        (const float*)d_in[3], (const float*)d_in[4],
        (const float*)d_in[5], (const float*)d_in[6],
        (const float*)d_in[7], (const float*)d_in[8],
        (const float*)d_in[9], (const float*)d_in[10],
        (float*)d_out);
}

// round 5
// speedup vs baseline: 1.2436x; 1.0889x over previous
#include <cuda_runtime.h>

// LSTMAutoencoder: B=4096, T=512, F=8, H=16
// enc LSTM -> hT -> repeat -> dec LSTM -> fused linear
//
// 16 lanes per batch element (lane j owns hidden unit j / gate rows j,16+j,
// 32+j,48+j). Each lane processes CH=2 independent batch elements (two
// interleavable dependency chains per warp for latency hiding). 32-thread
// blocks (2 lane-groups x 2 chains = 4 elements) -> 1024 blocks, balanced
// across 148 SMs. h broadcast via double-buffered smem row + one __syncwarp
// per step. All matvecs packed fp32x2 (FFMA2). Activation-arg scales
// (-log2e sigmoids, 2*log2e tanh) folded into weights/biases; c kept in the
// 2*log2e domain. Encoder x loads are software-pipelined 2 steps ahead.

using ull = unsigned long long;

#define Bsz 4096
#define Tsz 512
#define Fsz 8
#define Hsz 16
#define CH 2
#define GPB 2
#define EPB (GPB * CH)          // 4 elements per block
#define THREADS (GPB * 16)      // 32

#define L2E 1.4426950408889634f

__device__ __forceinline__ void fma2(ull& d, ull a, ull b) {
    asm("fma.rn.f32x2 %0, %1, %2, %0;" : "+l"(d) : "l"(a), "l"(b));
}
__device__ __forceinline__ ull fma2a(ull a, ull b, ull c) {
    ull r; asm("fma.rn.f32x2 %0, %1, %2, %3;" : "=l"(r) : "l"(a), "l"(b), "l"(c)); return r;
}
__device__ __forceinline__ ull mul2(ull a, ull b) {
    ull r; asm("mul.rn.f32x2 %0, %1, %2;" : "=l"(r) : "l"(a), "l"(b)); return r;
}
__device__ __forceinline__ ull pk(float lo, float hi) {
    ull r; asm("mov.b64 %0, {%1, %2};" : "=l"(r) : "f"(lo), "f"(hi)); return r;
}
__device__ __forceinline__ float redu(ull a) {   // lo + hi
    float lo, hi; asm("mov.b64 {%0, %1}, %2;" : "=f"(lo), "=f"(hi) : "l"(a));
    return lo + hi;
}
__device__ __forceinline__ float ex2f_(float x){ float y; asm("ex2.approx.f32 %0, %1;" : "=f"(y) : "f"(x)); return y; }
__device__ __forceinline__ float rcpf_(float x){ float y; asm("rcp.approx.f32 %0, %1;" : "=f"(y) : "f"(x)); return y; }

__global__ void __launch_bounds__(THREADS, 8)
lstm_ae(const float* __restrict__ x,
        const float* __restrict__ eWih, const float* __restrict__ eWhh,
        const float* __restrict__ eBih, const float* __restrict__ eBhh,
        const float* __restrict__ dWih, const float* __restrict__ dWhh,
        const float* __restrict__ dBih, const float* __restrict__ dBhh,
        const float* __restrict__ oW,  const float* __restrict__ oB,
        float* __restrict__ out)
{
    __shared__ __align__(16) float hbuf[2][EPB][Hsz];
    const int j   = threadIdx.x & 15;
    const int grp = threadIdx.x >> 4;      // 0..1
    const int e0  = grp * CH;              // element slot base within block
    const long b0 = (long)blockIdx.x * EPB + e0;

    const ull sgS = pk(-L2E, -L2E);
    const ull sgG = pk(2.0f*L2E, 2.0f*L2E);

    // ---------------- encoder weights (pre-scaled, packed; shared by chains)
    ull whh[4][8];
    ull wih[4][4];
    ull biaspk[4];
    #pragma unroll
    for (int g = 0; g < 4; ++g) {
        const ull  sc  = (g == 2) ? sgG : sgS;
        const float scf = (g == 2) ? 2.0f*L2E : -L2E;
        const int row = g * Hsz + j;
        const ull* wr = reinterpret_cast<const ull*>(eWhh + row * Hsz);
        #pragma unroll
        for (int p = 0; p < 8; ++p) whh[g][p] = mul2(wr[p], sc);
        const ull* wi = reinterpret_cast<const ull*>(eWih + row * Fsz);
        #pragma unroll
        for (int p = 0; p < 4; ++p) wih[g][p] = mul2(wi[p], sc);
        biaspk[g] = pk(scf * (eBih[row] + eBhh[row]), 0.0f);
    }

    hbuf[0][e0 + 0][j] = 0.0f;
    hbuf[0][e0 + 1][j] = 0.0f;
    __syncwarp();

    const longlong2* px0 = reinterpret_cast<const longlong2*>(x + (b0 + 0) * Tsz * Fsz);
    const longlong2* px1 = reinterpret_cast<const longlong2*>(x + (b0 + 1) * Tsz * Fsz);

    float cs[CH] = {0.0f, 0.0f};

    auto ldx = [](ull d[4], const longlong2* p) {
        longlong2 a = p[0], b2 = p[1];
        d[0] = (ull)a.x; d[1] = (ull)a.y; d[2] = (ull)b2.x; d[3] = (ull)b2.y;
    };

    // one encoder step for both chains: x regs already loaded
    auto estep = [&](ull xv[CH][4], int rb) {
        ull acc[CH][4];
        #pragma unroll
        for (int u = 0; u < CH; ++u) {
            #pragma unroll
            for (int g = 0; g < 4; ++g) acc[u][g] = fma2a(wih[g][0], xv[u][0], biaspk[g]);
            #pragma unroll
            for (int p = 1; p < 4; ++p) {
                #pragma unroll
                for (int g = 0; g < 4; ++g) fma2(acc[u][g], wih[g][p], xv[u][p]);
            }
        }
        #pragma unroll
        for (int u = 0; u < CH; ++u) {
            const ull* hr = reinterpret_cast<const ull*>(&hbuf[rb][e0 + u][0]);
            #pragma unroll
            for (int p = 0; p < 8; ++p) {
                ull hp = hr[p];
                fma2(acc[u][0], whh[0][p], hp); fma2(acc[u][1], whh[1][p], hp);
                fma2(acc[u][2], whh[2][p], hp); fma2(acc[u][3], whh[3][p], hp);
            }
        }
        float hh[CH];
        #pragma unroll
        for (int u = 0; u < CH; ++u) {
            const float r0 = rcpf_(1.0f + ex2f_(redu(acc[u][0])));
            const float r1 = rcpf_(1.0f + ex2f_(redu(acc[u][1])));
            const float r2 = rcpf_(1.0f + ex2f_(redu(acc[u][2])));
            const float r3 = rcpf_(1.0f + ex2f_(redu(acc[u][3])));
            const float gs = fmaf(r2, -4.0f*L2E, 2.0f*L2E);
            cs[u] = fmaf(r1, cs[u], r0 * gs);
            const float rc = rcpf_(1.0f + ex2f_(cs[u]));
            hh[u] = fmaf(r3 * rc, -2.0f, r3);
        }
        hbuf[rb ^ 1][e0 + 0][j] = hh[0];
        hbuf[rb ^ 1][e0 + 1][j] = hh[1];
        __syncwarp();
    };

    // x pipeline: xA holds step t, xB step t+1; preload t=0,1
    ull xA[CH][4], xB[CH][4];
    ldx(xA[0], px0); ldx(xA[1], px1);
    ldx(xB[0], px0 + 2); ldx(xB[1], px1 + 2);
    px0 += 4; px1 += 4;

    #pragma unroll 1
    for (int t = 0; t < Tsz; t += 2) {
        estep(xA, 0);
        if (t + 2 < Tsz) { ldx(xA[0], px0); ldx(xA[1], px1); px0 += 2; px1 += 2; }
        estep(xB, 1);
        if (t + 2 < Tsz) { ldx(xB[0], px0); ldx(xB[1], px1); px0 += 2; px1 += 2; }
    }
    // hT for both chains in hbuf[0]

    // ---------------- decoder prep ----------------
    ull xpdpk[CH][4];
    #pragma unroll
    for (int g = 0; g < 4; ++g) {
        const ull  sc  = (g == 2) ? sgG : sgS;
        const float scf = (g == 2) ? 2.0f*L2E : -L2E;
        const int row = g * Hsz + j;
        const float bsum = scf * (dBih[row] + dBhh[row]);
        const ull* wr = reinterpret_cast<const ull*>(dWih + row * Hsz);
        #pragma unroll
        for (int u = 0; u < CH; ++u) {
            const ull* hr0 = reinterpret_cast<const ull*>(&hbuf[0][e0 + u][0]);
            ull acc = pk(bsum, 0.0f);
            #pragma unroll
            for (int p = 0; p < 8; ++p) fma2(acc, mul2(wr[p], sc), hr0[p]);
            xpdpk[u][g] = pk(redu(acc), 0.0f);
        }
        const ull* wh = reinterpret_cast<const ull*>(dWhh + row * Hsz);
        #pragma unroll
        for (int p = 0; p < 8; ++p) whh[g][p] = mul2(wh[p], sc);
    }
    ull owp[8];
    const int f = j & 7;
    {
        const ull* orow = reinterpret_cast<const ull*>(oW + f * Hsz);
        #pragma unroll
        for (int p = 0; p < 8; ++p) owp[p] = orow[p];
    }
    const ull outbpk = pk(oB[f], 0.0f);

    cs[0] = 0.0f; cs[1] = 0.0f;
    __syncwarp();                 // all lanes done reading hT
    hbuf[0][e0 + 0][j] = 0.0f;
    hbuf[0][e0 + 1][j] = 0.0f;
    __syncwarp();

    float* po[CH];
    po[0] = out + (b0 + 0) * Tsz * Fsz + f;
    po[1] = out + (b0 + 1) * Tsz * Fsz + f;

    // decoder step: reads h_{t-1}; when doOut, emits output row for t-1
    // reusing the same h loads, then computes h_t.
    auto dstep = [&](int rb, bool doOut) {
        ull hp[CH][8];
        #pragma unroll
        for (int u = 0; u < CH; ++u) {
            const ull* hr = reinterpret_cast<const ull*>(&hbuf[rb][e0 + u][0]);
            #pragma unroll
            for (int p = 0; p < 8; ++p) hp[u][p] = hr[p];
        }
        if (doOut) {
            #pragma unroll
            for (int u = 0; u < CH; ++u) {
                ull oacc = fma2a(owp[0], hp[u][0], outbpk);
                #pragma unroll
                for (int p = 1; p < 8; ++p) fma2(oacc, owp[p], hp[u][p]);
                if (j < 8) { *po[u] = redu(oacc); }
                po[u] += Fsz;
            }
        }
        ull acc[CH][4];
        #pragma unroll
        for (int u = 0; u < CH; ++u) {
            #pragma unroll
            for (int g = 0; g < 4; ++g) acc[u][g] = fma2a(whh[g][0], hp[u][0], xpdpk[u][g]);
            #pragma unroll
            for (int p = 1; p < 8; ++p) {
                fma2(acc[u][0], whh[0][p], hp[u][p]); fma2(acc[u][1], whh[1][p], hp[u][p]);
                fma2(acc[u][2], whh[2][p], hp[u][p]); fma2(acc[u][3], whh[3][p], hp[u][p]);
            }
        }
        float hh[CH];
        #pragma unroll
        for (int u = 0; u < CH; ++u) {
            const float r0 = rcpf_(1.0f + ex2f_(redu(acc[u][0])));
            const float r1 = rcpf_(1.0f + ex2f_(redu(acc[u][1])));
            const float r2 = rcpf_(1.0f + ex2f_(redu(acc[u][2])));
            const float r3 = rcpf_(1.0f + ex2f_(redu(acc[u][3])));
            const float gs = fmaf(r2, -4.0f*L2E, 2.0f*L2E);
            cs[u] = fmaf(r1, cs[u], r0 * gs);
            const float rc = rcpf_(1.0f + ex2f_(cs[u]));
            hh[u] = fmaf(r3 * rc, -2.0f, r3);
        }
        hbuf[rb ^ 1][e0 + 0][j] = hh[0];
        hbuf[rb ^ 1][e0 + 1][j] = hh[1];
        __syncwarp();
    };

    dstep(0, false);   // t=0 (no previous h to emit)
    dstep(1, true);    // t=1, emits row 0
    #pragma unroll 1
    for (int t = 2; t < Tsz; t += 2) {
        dstep(0, true);
        dstep(1, true);
    }
    // emit final row (h_{511} in hbuf[0])
    #pragma unroll
    for (int u = 0; u < CH; ++u) {
        const ull* hr = reinterpret_cast<const ull*>(&hbuf[0][e0 + u][0]);
        ull oacc = fma2a(owp[0], hr[0], outbpk);
        #pragma unroll
        for (int p = 1; p < 8; ++p) fma2(oacc, owp[p], hr[p]);
        if (j < 8) { *po[u] = redu(oacc); }
    }
}

extern "C" void kernel_launch(void* const* d_in, const int* in_sizes, int n_in,
                              void* d_out, int out_size) {
    (void)in_sizes; (void)n_in; (void)out_size;
    lstm_ae<<<Bsz / EPB, THREADS>>>(
        (const float*)d_in[0],
        (const float*)d_in[1], (const float*)d_in[2],
        (const float*)d_in[3], (const float*)d_in[4],
        (const float*)d_in[5], (const float*)d_in[6],
        (const float*)d_in[7], (const float*)d_in[8],
        (const float*)d_in[9], (const float*)d_in[10],
        (float*)d_out);
}